// round 12
// baseline (speedup 1.0000x reference)
#include <cuda_runtime.h>
#include <cuda_fp16.h>
#include <cuda_bf16.h>

// CBOW hierarchical-softmax loss.
// Inputs (metadata order):
//   d_in[0] context_idxs  int32 [B, C]   B=65536, C=10
//   d_in[1] path_nodes    int32 [B, D]   D=18
//   d_in[2] codes         int32 [B, D]
//   d_in[3] in_embed      f32   [V, E]   V=100000, E=128
//   d_in[4] node_embed    f32   [N, E]   N=99999
// Output: loss f32 [B]
//
// R12 = R11 with the scratch-array sizing bug fixed: a fp16 row of E=128
//       halves is E/4 = 32 uint2, so each table needs V*E/4 uint2 (25.6MB),
//       not V*E/8. R11's convert kernel wrote 2x past the array -> illegal
//       memory access. Theory unchanged: kernel is LTS-delivery-bound
//       (~12.7TB/s); fp16 tables halve gathered bytes (940MB -> 470MB)
//       -> main pass ~37us + convert prologue ~15-19us.

#define B_ 65536
#define C_ 10
#define D_ 18
#define E_ 128
#define V_ 100000
#define N_ 99999
#define EPS_ 1e-9f

typedef unsigned long long u64;

// fp16 copies of the tables (scratch; __device__ globals are the sanctioned
// no-alloc scratch mechanism). One row = E_/4 = 32 uint2 (4 halves per uint2).
__device__ uint2 g_in16[V_ * E_ / 4];   // 25.6 MB
__device__ uint2 g_nd16[N_ * E_ / 4];   // 25.6 MB

__device__ __forceinline__ u64 f32x2_add(u64 a, u64 b) {
    u64 r; asm("add.rn.f32x2 %0, %1, %2;" : "=l"(r) : "l"(a), "l"(b)); return r;
}
__device__ __forceinline__ u64 pack2(float lo, float hi) {
    u64 r; asm("mov.b64 %0, {%1, %2};" : "=l"(r) : "f"(lo), "f"(hi)); return r;
}
__device__ __forceinline__ float2 unpack2(u64 v) {
    float2 f; asm("mov.b64 {%0, %1}, %2;" : "=f"(f.x), "=f"(f.y) : "l"(v)); return f;
}
__device__ __forceinline__ u64 shfl_xor_u64(u64 v, int o) {
    uint2 t; asm("mov.b64 {%0, %1}, %2;" : "=r"(t.x), "=r"(t.y) : "l"(v));
    t.x = __shfl_xor_sync(0xFFFFFFFFu, t.x, o);
    t.y = __shfl_xor_sync(0xFFFFFFFFu, t.y, o);
    u64 r; asm("mov.b64 %0, {%1, %2};" : "=l"(r) : "r"(t.x), "r"(t.y));
    return r;
}

// ---------------- prologue: f32 tables -> fp16 scratch ----------------
// One float4 (4 floats) -> one uint2 (4 halves); i indexes float4/uint2 pairs.
__global__ void __launch_bounds__(256) convert_kernel(
    const float4* __restrict__ inA,   // in_embed, V_*E_/4 float4
    const float4* __restrict__ inB)   // node_embed, N_*E_/4 float4
{
    const int nA = V_ * E_ / 4;
    const int nTot = nA + N_ * E_ / 4;
    int i = blockIdx.x * blockDim.x + threadIdx.x;
    if (i >= nTot) return;

    float4 f;
    uint2* dst;
    if (i < nA) {
        f = __ldg(&inA[i]);
        dst = &g_in16[i];
    } else {
        f = __ldg(&inB[i - nA]);
        dst = &g_nd16[i - nA];
    }
    __half2 h0 = __floats2half2_rn(f.x, f.y);
    __half2 h1 = __floats2half2_rn(f.z, f.w);
    *dst = make_uint2(*reinterpret_cast<unsigned*>(&h0),
                      *reinterpret_cast<unsigned*>(&h1));
}

// ---------------- main: gathers on fp16 rows (256B each) ----------------
__global__ void __launch_bounds__(256) cbow_hs_kernel(
    const int* __restrict__ ctx,
    const int* __restrict__ path,
    const int* __restrict__ codes,
    float* __restrict__ out)
{
    const int warp = (blockIdx.x * blockDim.x + threadIdx.x) >> 5;
    const int lane = threadIdx.x & 31;
    if (warp >= B_) return;

    // fp16 row = 32 uint2 (8B per lane, cols 4l..4l+3)
    const uint2* __restrict__ in16 = g_in16;
    const uint2* __restrict__ nd16 = g_nd16;

    // ---- per-lane code: one coalesced 72B LDG per warp ----
    int code_l = 0;
    if (lane < D_) code_l = __ldg(&codes[warp * D_ + lane]);

    // ---- context indices: 5 x int2 ----
    const int2* __restrict__ ctx2 = reinterpret_cast<const int2*>(ctx + warp * C_);
    int cidx[C_];
#pragma unroll
    for (int j = 0; j < C_ / 2; j++) {
        int2 c = __ldg(&ctx2[j]);
        cidx[2 * j]     = c.x;
        cidx[2 * j + 1] = c.y;
    }

    // ---- context mean: 10 independent 256B row gathers ----
    float v0 = 0.f, v1 = 0.f, v2 = 0.f, v3 = 0.f;
#pragma unroll
    for (int j = 0; j < C_; j++) {
        uint2 raw = __ldg(&in16[cidx[j] * (E_ / 4) + lane]);
        __half2 h0 = *reinterpret_cast<__half2*>(&raw.x);
        __half2 h1 = *reinterpret_cast<__half2*>(&raw.y);
        float2 a = __half22float2(h0);
        float2 b = __half22float2(h1);
        v0 += a.x; v1 += a.y; v2 += b.x; v3 += b.y;
    }
    const float inv = 1.0f / (float)C_;
    v0 *= inv; v1 *= inv; v2 *= inv; v3 *= inv;

    // ---- path indices: 9 x int2 ----
    const int2* __restrict__ pn2 = reinterpret_cast<const int2*>(path + warp * D_);
    int pn[D_];
#pragma unroll
    for (int j = 0; j < D_ / 2; j++) {
        int2 p = __ldg(&pn2[j]);
        pn[2 * j] = p.x; pn[2 * j + 1] = p.y;
    }

    // ---- 18 independent node-row gathers -> 9 packed per-lane partials ----
    u64 pair[D_ / 2];
#pragma unroll
    for (int j = 0; j < D_ / 2; j++) {
        uint2 r0 = __ldg(&nd16[pn[2 * j]     * (E_ / 4) + lane]);
        uint2 r1 = __ldg(&nd16[pn[2 * j + 1] * (E_ / 4) + lane]);
        __half2 h00 = *reinterpret_cast<__half2*>(&r0.x);
        __half2 h01 = *reinterpret_cast<__half2*>(&r0.y);
        __half2 h10 = *reinterpret_cast<__half2*>(&r1.x);
        __half2 h11 = *reinterpret_cast<__half2*>(&r1.y);
        float2 a0 = __half22float2(h00), b0 = __half22float2(h01);
        float2 a1 = __half22float2(h10), b1 = __half22float2(h11);
        float p0 = fmaf(a0.x, v0, fmaf(a0.y, v1, fmaf(b0.x, v2, b0.y * v3)));
        float p1 = fmaf(a1.x, v0, fmaf(a1.y, v1, fmaf(b1.x, v2, b1.y * v3)));
        pair[j] = pack2(p0, p1);
    }

    // ---- pair-packed butterfly: 9 u64 reduced across lanes in 5 steps ----
#pragma unroll
    for (int o = 16; o > 0; o >>= 1) {
#pragma unroll
        for (int j = 0; j < D_ / 2; j++)
            pair[j] = f32x2_add(pair[j], shfl_xor_u64(pair[j], o));
    }

    // ---- lane d takes logit s_d ----
    const int mypair_idx = lane >> 1;
    u64 mypair = pair[0];
#pragma unroll
    for (int j = 1; j < D_ / 2; j++)
        mypair = (j == mypair_idx) ? pair[j] : mypair;
    float2 sp = unpack2(mypair);
    float s = (lane & 1) ? sp.y : sp.x;

    // ---- epilogue once per warp (3 MUFU total) ----
    float x = code_l ? s : -s;   // p = sigmoid(x) if code==1 else sigmoid(-x)
    float sig = __fdividef(1.0f, 1.0f + __expf(-x));
    float term = __logf(sig + EPS_);
    term = (lane < D_) ? term : 0.f;

#pragma unroll
    for (int o = 16; o > 0; o >>= 1)
        term += __shfl_xor_sync(0xFFFFFFFFu, term, o);

    if (lane == 0)
        out[warp] = -term;
}

extern "C" void kernel_launch(void* const* d_in, const int* in_sizes, int n_in,
                              void* d_out, int out_size)
{
    const int*   ctx      = (const int*)d_in[0];
    const int*   path     = (const int*)d_in[1];
    const int*   codes    = (const int*)d_in[2];
    const float* in_emb   = (const float*)d_in[3];
    const float* node_emb = (const float*)d_in[4];
    float*       out      = (float*)d_out;

    // 1) convert both tables to fp16 scratch
    {
        const int nTot = (V_ + N_) * E_ / 4;   // float4 count
        const int threads = 256;
        const int blocks = (nTot + threads - 1) / threads;
        convert_kernel<<<blocks, threads>>>(
            reinterpret_cast<const float4*>(in_emb),
            reinterpret_cast<const float4*>(node_emb));
    }

    // 2) main gather pass on fp16 rows
    {
        const int threads = 256;               // 8 warps/block
        const int total   = B_ * 32;
        const int blocks  = (total + threads - 1) / threads;
        cbow_hs_kernel<<<blocks, threads>>>(ctx, path, codes, out);
    }
}